// round 8
// baseline (speedup 1.0000x reference)
#include <cuda_runtime.h>
#include <math_constants.h>

// ProbAttention: B=4, L=4096, H=8, D=64, FACTOR=5
#define B_ 4
#define L_ 4096
#define H_ 8
#define D_ 64
#define SK_ 45
#define U_  45
#define NSPLIT 64
#define KC 64          // keys per split = L_/NSPLIT
#define PADK 68
#define NCH 16         // key chunks for scatter-M
#define CR  256        // keys per chunk

// Scratch (device globals; no allocation allowed)
__device__ int   g_Mtop[B_ * H_ * U_];
__device__ float g_vmean[B_ * H_ * D_];
__device__ float g_pm[B_ * H_ * NSPLIT * U_];
__device__ float g_ps[B_ * H_ * NSPLIT * U_];
__device__ float g_pacc[B_ * H_ * NSPLIT * U_ * D_];   // 23.6 MB
__device__ int   g_blist[L_ * SK_];       // sample ids grouped by chunk
__device__ int   g_boff[L_ * 17];         // per-query chunk offsets
__device__ float g_pmax[NCH * B_ * H_ * L_];  // 8 MB
__device__ float g_psum[NCH * B_ * H_ * L_];  // 8 MB

typedef unsigned long long ull;
__device__ __forceinline__ float lo2(ull v) { return __uint_as_float((unsigned)v); }
__device__ __forceinline__ float hi2(ull v) { return __uint_as_float((unsigned)(v >> 32)); }
#define FMA2(acc, a, b) asm("fma.rn.f32x2 %0, %1, %2, %0;" : "+l"(acc) : "l"(a), "l"(b))
#define DUP2(out, x) asm("mov.b64 %0, {%1, %1};" : "=l"(out) : "r"(__float_as_uint(x)))

__device__ __forceinline__ unsigned smem_u32(const void* p) {
    return (unsigned)__cvta_generic_to_shared(p);
}

// ---------------------------------------------------------------------------
// Kernel A: bucket sample indices by key-chunk (+ zero vmean).
// 16 blocks x 256 threads; one thread per query l.
// ---------------------------------------------------------------------------
__global__ void __launch_bounds__(256) kernel_bucket(const int* __restrict__ idx) {
    __shared__ int scnt[256][17];
    int t = threadIdx.x;
    int l = blockIdx.x * 256 + t;
#pragma unroll
    for (int c = 0; c < 17; c++) scnt[t][c] = 0;
    const int* ip = idx + l * SK_;
#pragma unroll 5
    for (int s = 0; s < SK_; s++) scnt[t][ip[s] >> 8]++;
    int acc = 0;
#pragma unroll
    for (int c = 0; c < NCH; c++) {
        int v = scnt[t][c];
        g_boff[l * 17 + c] = acc;
        scnt[t][c] = acc;
        acc += v;
    }
    g_boff[l * 17 + 16] = SK_;
#pragma unroll 5
    for (int s = 0; s < SK_; s++) {
        int v = ip[s];
        int c = v >> 8;
        int p = scnt[t][c]++;
        g_blist[l * SK_ + p] = v;
    }
    if (blockIdx.x == 0)
        for (int i = t; i < B_ * H_ * D_; i += 256) g_vmean[i] = 0.0f;
}

// ---------------------------------------------------------------------------
// Kernel B: scatter-M. grid = NCH*32 blocks (c = x&15, bh = x>>4), 256 thr.
// K chunk (256 rows, pad 68) in smem; 4-lane groups per query (lane li owns
// floats [li*16, li*16+16)); Q in regs double-buffered; dots from smem.
// ---------------------------------------------------------------------------
#define M2_SMEM (CR * PADK * 4)   // 69632 B

__global__ void __launch_bounds__(256) kernel_M2(const float* __restrict__ Q,
                                                 const float* __restrict__ K) {
    extern __shared__ float sK[];           // [CR][PADK]
    int blk = blockIdx.x;
    int c = blk & 15;
    int bh = blk >> 4;
    int h = bh & 7, b = bh >> 3;
    int t = threadIdx.x;

    // Load K chunk (coalesced float4)
    for (int i = t; i < CR * 16; i += 256) {
        int row = i >> 4, col = i & 15;
        float4 v = *(const float4*)(K + ((size_t)(b * L_ + c * CR + row) * H_ + h) * D_ + col * 4);
        *(float4*)&sK[row * PADK + col * 4] = v;
    }
    __syncthreads();

    int w = t >> 5, lane = t & 31;
    int g = lane >> 2, li = lane & 3;
    unsigned gmask = 0xFu << (g * 4);

    // q registers: 4 ulonglong2 = 16 floats per lane (full 64-dim coverage
    // across the 4-lane group), double-buffered.
    ulonglong2 qv[4];
    {
        int l = w * 8 + g;
        const ulonglong2* qp =
            (const ulonglong2*)(Q + ((size_t)(b * L_ + l) * H_ + h) * D_ + li * 16);
#pragma unroll
        for (int jq = 0; jq < 4; jq++) qv[jq] = qp[jq];
    }
    for (int i = 0; i < 64; i++) {
        int l = w * 8 + g + i * 64;
        ulonglong2 nv[4];
#pragma unroll
        for (int jq = 0; jq < 4; jq++) nv[jq] = qv[jq];
        if (i < 63) {
            const ulonglong2* np =
                (const ulonglong2*)(Q + ((size_t)(b * L_ + l + 64) * H_ + h) * D_ + li * 16);
#pragma unroll
            for (int jq = 0; jq < 4; jq++) nv[jq] = np[jq];
        }
        int st = g_boff[l * 17 + c];
        int en = g_boff[l * 17 + c + 1];
        float mx = -CUDART_INF_F, sm = 0.0f;
        for (int r = st; r < en; r++) {
            int kr = g_blist[l * SK_ + r] & (CR - 1);
            const ulonglong2* kp = (const ulonglong2*)(sK + kr * PADK + li * 16);
            ull acc = 0;
#pragma unroll
            for (int jq = 0; jq < 4; jq++) {
                ulonglong2 kv = kp[jq];
                FMA2(acc, qv[jq].x, kv.x);
                FMA2(acc, qv[jq].y, kv.y);
            }
            float d = lo2(acc) + hi2(acc);
            d += __shfl_xor_sync(gmask, d, 1);
            d += __shfl_xor_sync(gmask, d, 2);
            mx = fmaxf(mx, d); sm += d;
        }
        if (li == 0) {
            g_pmax[((c << 5) + bh) * L_ + l] = mx;
            g_psum[((c << 5) + bh) * L_ + l] = sm;
        }
#pragma unroll
        for (int jq = 0; jq < 4; jq++) qv[jq] = nv[jq];
    }
}

// ---------------------------------------------------------------------------
// Kernel 2: top-U per (b,h): inline chunk-reduce of (pmax,psum) -> M,
// then two-level radix histogram + exact tail select.
// ---------------------------------------------------------------------------
__device__ __forceinline__ unsigned f2key(float f) {
    unsigned u = __float_as_uint(f);
    return (u & 0x80000000u) ? ~u : (u | 0x80000000u);
}

__global__ void __launch_bounds__(256) kernel_topk() {
    __shared__ unsigned skeys[L_];
    __shared__ int hist[256];
    __shared__ unsigned candKey[1024];
    __shared__ int candIdx[1024];
    __shared__ int sT1, sN1, sT2;
    __shared__ int cSel, cCand;
    __shared__ unsigned rk[256];
    __shared__ int ri[256];

    int bh = blockIdx.x;
    int t = threadIdx.x;
    for (int i = t; i < L_; i += 256) {
        float mx = -CUDART_INF_F, sm = 0.0f;
#pragma unroll
        for (int c = 0; c < NCH; c++) {
            mx = fmaxf(mx, g_pmax[((c << 5) + bh) * L_ + i]);
            sm += g_psum[((c << 5) + bh) * L_ + i];
        }
        skeys[i] = f2key(mx - sm * (1.0f / (float)L_));
    }
    hist[t] = 0;
    __syncthreads();

    for (int i = t; i < L_; i += 256) atomicAdd(&hist[skeys[i] >> 24], 1);
    __syncthreads();
    if (t == 0) {
        int acc = 0;
        for (int bin = 255; bin >= 0; bin--) {
            if (acc + hist[bin] >= U_) { sT1 = bin; sN1 = acc; break; }
            acc += hist[bin];
        }
    }
    __syncthreads();
    int T1 = sT1, n1 = sN1;
    hist[t] = 0;
    __syncthreads();

    for (int i = t; i < L_; i += 256)
        if ((int)(skeys[i] >> 24) == T1) atomicAdd(&hist[(skeys[i] >> 16) & 255], 1);
    __syncthreads();
    if (t == 0) {
        int acc = n1;
        for (int bin = 255; bin >= 0; bin--) {
            if (acc + hist[bin] >= U_) { sT2 = bin; break; }
            acc += hist[bin];
        }
        cSel = 0; cCand = 0;
    }
    __syncthreads();
    unsigned TH16 = ((unsigned)T1 << 8) | (unsigned)sT2;

    for (int i = t; i < L_; i += 256) {
        unsigned k16 = skeys[i] >> 16;
        if (k16 > TH16) {
            int pos = atomicAdd(&cSel, 1);
            g_Mtop[bh * U_ + pos] = i;
        } else if (k16 == TH16) {
            int pos = atomicAdd(&cCand, 1);
            if (pos < 1024) { candKey[pos] = skeys[i]; candIdx[pos] = i; }
        }
    }
    __syncthreads();
    int ndef = cSel;
    int need = U_ - ndef;
    int nc = (cCand < 1024) ? cCand : 1024;

    for (int it = 0; it < need; it++) {
        unsigned best = 0; int bi = -1;
        for (int jj = t; jj < nc; jj += 256) {
            unsigned v = candKey[jj];
            if (v > best) { best = v; bi = jj; }
        }
        rk[t] = best; ri[t] = bi;
        __syncthreads();
        for (int s = 128; s; s >>= 1) {
            if (t < s && rk[t + s] > rk[t]) { rk[t] = rk[t + s]; ri[t] = ri[t + s]; }
            __syncthreads();
        }
        if (t == 0) {
            g_Mtop[bh * U_ + ndef + it] = candIdx[ri[0]];
            candKey[ri[0]] = 0;
        }
        __syncthreads();
    }
}

// ---------------------------------------------------------------------------
// Kernel 3: V mean partial sums (vmean zeroed by kernel_bucket)
// ---------------------------------------------------------------------------
__global__ void __launch_bounds__(256) kernel_mean_part(const float* __restrict__ V) {
    int blk = blockIdx.x;              // 1024 blocks
    int seg = blk & 31;
    int bh = blk >> 5;
    int h = bh & (H_ - 1);
    int b = bh >> 3;
    int t = threadIdx.x;
    int d4 = t & 15;
    int sub = t >> 4;
    int l0 = seg * 128;
    const float4* V4 = (const float4*)V;
    float ax = 0.f, ay = 0.f, az = 0.f, aw = 0.f;
#pragma unroll
    for (int i = 0; i < 8; i++) {
        int l = l0 + sub + i * 16;
        float4 v = V4[((size_t)(b * L_ + l) * H_ + h) * 16 + d4];
        ax += v.x; ay += v.y; az += v.z; aw += v.w;
    }
    __shared__ float4 s[16][16];
    s[sub][d4] = make_float4(ax, ay, az, aw);
    __syncthreads();
    if (t < 16) {
        float tx = 0.f, ty = 0.f, tz = 0.f, tw = 0.f;
#pragma unroll
        for (int jj = 0; jj < 16; jj++) {
            float4 v = s[jj][t];
            tx += v.x; ty += v.y; tz += v.z; tw += v.w;
        }
        atomicAdd(&g_vmean[bh * D_ + t * 4 + 0], tx);
        atomicAdd(&g_vmean[bh * D_ + t * 4 + 1], ty);
        atomicAdd(&g_vmean[bh * D_ + t * 4 + 2], tz);
        atomicAdd(&g_vmean[bh * D_ + t * 4 + 3], tw);
    }
}

// ---------------------------------------------------------------------------
// Kernel 4: fill out with V-mean broadcast (float4 stores)
// ---------------------------------------------------------------------------
__global__ void kernel_fill(float* __restrict__ out) {
    unsigned i = blockIdx.x * blockDim.x + threadIdx.x;  // float4 index
    int d4 = i & 15;
    int h = (i >> 4) & 7;
    int b = i >> 19;
    const float4* vm4 = (const float4*)g_vmean;
    float4 v = vm4[(b * H_ + h) * 16 + d4];
    const float inv = 1.0f / (float)L_;
    ((float4*)out)[i] = make_float4(v.x * inv, v.y * inv, v.z * inv, v.w * inv);
}

// ---------------------------------------------------------------------------
// Kernel 5: split-KV attention (round-6 version, unchanged).
// ---------------------------------------------------------------------------
#define OFF_V   (64 * PADK)
#define OFF_QE  (OFF_V + 64 * PADK)
#define OFF_MT  (OFF_QE + 48 * 64)
#define SMEM_FLOATS (OFF_MT + 64)
#define SMEM_BYTES  (SMEM_FLOATS * 4)

__global__ void __launch_bounds__(256) kernel_attn_part(
        const float* __restrict__ Q,
        const float* __restrict__ K,
        const float* __restrict__ V) {
    extern __shared__ float smem[];
    float* sKT = smem;                  // [64][PADK]  K transposed [d][k]
    float* sV  = smem + OFF_V;          // [64][PADK]  V natural   [k][d]
    float* sQE = smem + OFF_QE;         // [48][64]    Q rows, then E rows
    int*   sMt = (int*)(smem + OFF_MT);

    int bh = blockIdx.x >> 6;
    int sp = blockIdx.x & 63;
    int h = bh & 7, b = bh >> 3;
    int k0 = sp * KC;
    int t = threadIdx.x;

    {
        const char* vbase = (const char*)(V + ((size_t)(b * L_ + k0) * H_ + h) * D_);
#pragma unroll
        for (int i = 0; i < 4; i++) {
            int e = t + i * 256;
            int row = e >> 4, c = e & 15;
            unsigned dst = smem_u32(sV + row * PADK + c * 4);
            const char* src = vbase + (size_t)row * (H_ * D_ * 4) + c * 16;
            asm volatile("cp.async.cg.shared.global [%0], [%1], 16;"
                         :: "r"(dst), "l"(src));
        }
        asm volatile("cp.async.commit_group;");
    }

    if (t < U_) sMt[t] = g_Mtop[bh * U_ + t];
    __syncthreads();

#pragma unroll
    for (int i = 0; i < 3; i++) {
        int e = t + i * 256;
        int u = e >> 4, c = e & 15;
        float4 q = make_float4(0.f, 0.f, 0.f, 0.f);
        if (u < U_)
            q = *(const float4*)(Q + ((b * L_ + sMt[u]) * H_ + h) * D_ + c * 4);
        *(float4*)(sQE + u * 64 + c * 4) = q;
    }
#pragma unroll
    for (int i = 0; i < 16; i++) {
        int e = t + i * 256;
        int k = e >> 6, d = e & 63;
        sKT[d * PADK + k] = K[((b * L_ + k0 + k) * H_ + h) * D_ + d];
    }
    __syncthreads();

    int kt = t & 15, ut = t >> 4;
    int kk = kt * 4, u0 = ut * 3;

    ull a00 = 0, a01 = 0, a10 = 0, a11 = 0, a20 = 0, a21 = 0;
    {
        const float* q0p = sQE + (u0 + 0) * 64;
        const float* q1p = sQE + (u0 + 1) * 64;
        const float* q2p = sQE + (u0 + 2) * 64;
#pragma unroll 8
        for (int d = 0; d < 64; d++) {
            ulonglong2 kv = *(const ulonglong2*)&sKT[d * PADK + kk];
            ull q0, q1, q2;
            DUP2(q0, q0p[d]); DUP2(q1, q1p[d]); DUP2(q2, q2p[d]);
            FMA2(a00, q0, kv.x); FMA2(a01, q0, kv.y);
            FMA2(a10, q1, kv.x); FMA2(a11, q1, kv.y);
            FMA2(a20, q2, kv.x); FMA2(a21, q2, kv.y);
        }
    }

    float ev[3][4];
    {
        const float sc = 0.125f;
        ull ra[3][2] = {{a00, a01}, {a10, a11}, {a20, a21}};
#pragma unroll
        for (int jj = 0; jj < 3; jj++) {
            float s0 = lo2(ra[jj][0]) * sc, s1 = hi2(ra[jj][0]) * sc;
            float s2 = lo2(ra[jj][1]) * sc, s3 = hi2(ra[jj][1]) * sc;
            float mm = fmaxf(fmaxf(s0, s1), fmaxf(s2, s3));
            mm = fmaxf(mm, __shfl_xor_sync(0xffffffffu, mm, 1));
            mm = fmaxf(mm, __shfl_xor_sync(0xffffffffu, mm, 2));
            mm = fmaxf(mm, __shfl_xor_sync(0xffffffffu, mm, 4));
            mm = fmaxf(mm, __shfl_xor_sync(0xffffffffu, mm, 8));
            float e0 = __expf(s0 - mm), e1 = __expf(s1 - mm);
            float e2 = __expf(s2 - mm), e3 = __expf(s3 - mm);
            float ss = (e0 + e1) + (e2 + e3);
            ss += __shfl_xor_sync(0xffffffffu, ss, 1);
            ss += __shfl_xor_sync(0xffffffffu, ss, 2);
            ss += __shfl_xor_sync(0xffffffffu, ss, 4);
            ss += __shfl_xor_sync(0xffffffffu, ss, 8);
            ev[jj][0] = e0; ev[jj][1] = e1; ev[jj][2] = e2; ev[jj][3] = e3;
            int u = u0 + jj;
            if (kt == 0 && u < U_) {
                g_pm[(bh * NSPLIT + sp) * U_ + u] = mm;
                g_ps[(bh * NSPLIT + sp) * U_ + u] = ss;
            }
        }
    }
    __syncthreads();

#pragma unroll
    for (int jj = 0; jj < 3; jj++)
        *(float4*)(sQE + (u0 + jj) * 64 + kk) =
            make_float4(ev[jj][0], ev[jj][1], ev[jj][2], ev[jj][3]);

    asm volatile("cp.async.wait_group 0;");
    __syncthreads();

    {
        int dd = kk;
        ull c00 = 0, c01 = 0, c10 = 0, c11 = 0, c20 = 0, c21 = 0;
        const float* e0p = sQE + (u0 + 0) * 64;
        const float* e1p = sQE + (u0 + 1) * 64;
        const float* e2p = sQE + (u0 + 2) * 64;
#pragma unroll 8
        for (int k = 0; k < 64; k++) {
            ulonglong2 vv = *(const ulonglong2*)&sV[k * PADK + dd];
            ull e0, e1, e2;
            DUP2(e0, e0p[k]); DUP2(e1, e1p[k]); DUP2(e2, e2p[k]);
            FMA2(c00, e0, vv.x); FMA2(c01, e0, vv.y);
            FMA2(c10, e1, vv.x); FMA2(c11, e1, vv.y);
            FMA2(c20, e2, vv.x); FMA2(c21, e2, vv.y);
        }
        float* pa = g_pacc + (size_t)(bh * NSPLIT + sp) * U_ * D_;
        if (u0 + 0 < U_)
            *(float4*)&pa[(u0 + 0) * D_ + dd] =
                make_float4(lo2(c00), hi2(c00), lo2(c01), hi2(c01));
        if (u0 + 1 < U_)
            *(float4*)&pa[(u0 + 1) * D_ + dd] =
                make_float4(lo2(c10), hi2(c10), lo2(c11), hi2(c11));
        if (u0 + 2 < U_)
            *(float4*)&pa[(u0 + 2) * D_ + dd] =
                make_float4(lo2(c20), hi2(c20), lo2(c21), hi2(c21));
    }
}

// ---------------------------------------------------------------------------
// Kernel 6: combine partials. grid = (U_, B*H), 64 threads.
// ---------------------------------------------------------------------------
__global__ void __launch_bounds__(64) kernel_combine(float* __restrict__ out) {
    __shared__ float sw[NSPLIT];
    __shared__ float red[64];
    int u = blockIdx.x;
    int bh = blockIdx.y;
    int h = bh & 7, b = bh >> 3;
    int t = threadIdx.x;

    float m = g_pm[(bh * NSPLIT + t) * U_ + u];
    float s = g_ps[(bh * NSPLIT + t) * U_ + u];
    red[t] = m;
    __syncthreads();
    for (int st = 32; st; st >>= 1) {
        if (t < st) red[t] = fmaxf(red[t], red[t + st]);
        __syncthreads();
    }
    float M = red[0];
    __syncthreads();
    float e = __expf(m - M);
    red[t] = e * s;
    __syncthreads();
    for (int st = 32; st; st >>= 1) {
        if (t < st) red[t] += red[t + st];
        __syncthreads();
    }
    float inv = 1.0f / red[0];
    sw[t] = e * inv;
    __syncthreads();

    float acc = 0.0f;
    const float* pa = g_pacc + (size_t)bh * NSPLIT * U_ * D_ + u * D_ + t;
#pragma unroll 8
    for (int sp = 0; sp < NSPLIT; sp++)
        acc += pa[(size_t)sp * U_ * D_] * sw[sp];
    int lsel = g_Mtop[bh * U_ + u];
    out[((b * L_ + lsel) * H_ + h) * D_ + t] = acc;
}

// ---------------------------------------------------------------------------
extern "C" void kernel_launch(void* const* d_in, const int* in_sizes, int n_in,
                              void* d_out, int out_size) {
    const float* Q = (const float*)d_in[0];
    const float* K = (const float*)d_in[1];
    const float* V = (const float*)d_in[2];
    const int* idx = (const int*)d_in[3];   // int32 (JAX x64 disabled)
    float* out = (float*)d_out;

    cudaFuncSetAttribute((const void*)kernel_M2,
                         cudaFuncAttributeMaxDynamicSharedMemorySize, M2_SMEM);
    cudaFuncSetAttribute((const void*)kernel_attn_part,
                         cudaFuncAttributeMaxDynamicSharedMemorySize, SMEM_BYTES);

    // Order: ncu capture slot (position 4) lands on kernel_M2.
    kernel_bucket<<<16, 256>>>(idx);
    kernel_mean_part<<<B_ * H_ * 32, 256>>>(V);
    kernel_fill<<<(B_ * L_ * H_ * D_ / 4 + 255) / 256, 256>>>(out);
    kernel_M2<<<NCH * B_ * H_, 256, M2_SMEM>>>(Q, K);
    kernel_topk<<<B_ * H_, 256>>>();
    kernel_attn_part<<<B_ * H_ * NSPLIT, 256, SMEM_BYTES>>>(Q, K, V);
    kernel_combine<<<dim3(U_, B_ * H_), 64>>>(out);
}

// round 9
// speedup vs baseline: 2.0687x; 2.0687x over previous
#include <cuda_runtime.h>
#include <math_constants.h>

// ProbAttention: B=4, L=4096, H=8, D=64, FACTOR=5
#define B_ 4
#define L_ 4096
#define H_ 8
#define D_ 64
#define SK_ 45
#define U_  45
#define NSPLIT 32
#define KC 128         // keys per split = L_/NSPLIT
#define PADKT 132      // sKT row pad (k dim 128)
#define PADV 68        // sV row pad (d dim 64)

// Scratch (device globals; no allocation allowed)
__device__ float g_M[B_ * H_ * L_];
__device__ int   g_Mtop[B_ * H_ * U_];
__device__ float g_vmean[B_ * H_ * D_];
__device__ float g_pm[B_ * H_ * NSPLIT * U_];
__device__ float g_ps[B_ * H_ * NSPLIT * U_];
__device__ float g_pacc[B_ * H_ * NSPLIT * U_ * D_];   // 11.8 MB

typedef unsigned long long ull;
__device__ __forceinline__ float lo2(ull v) { return __uint_as_float((unsigned)v); }
__device__ __forceinline__ float hi2(ull v) { return __uint_as_float((unsigned)(v >> 32)); }
#define FMA2(acc, a, b) asm("fma.rn.f32x2 %0, %1, %2, %0;" : "+l"(acc) : "l"(a), "l"(b))
#define DUP2(out, x) asm("mov.b64 %0, {%1, %1};" : "=l"(out) : "r"(__float_as_uint(x)))

__device__ __forceinline__ unsigned smem_u32(const void* p) {
    return (unsigned)__cvta_generic_to_shared(p);
}

// ---------------------------------------------------------------------------
// Kernel 1: M[b,h,l] = max_s(Q·K_s) - (1/L)*sum_s(Q·K_s)
// Gather version — measured AT the LTS cap (1.51 GB @ ~12 TB/s = 127us).
// ---------------------------------------------------------------------------
__global__ void __launch_bounds__(256) kernel_M(const float* __restrict__ Q,
                                                const float* __restrict__ K,
                                                const int* __restrict__ idx) {
    int j = (blockIdx.x * 111) & 16383;      // bijective remap
    int w = j * 8 + (threadIdx.x >> 5);
    int lane = threadIdx.x & 31;
    int li = lane & 7;
    int g  = lane >> 3;
    int l = w & (L_ - 1);
    int h = (w >> 12) & (H_ - 1);
    int b = w >> 15;

    const float4* q4 = (const float4*)(Q + ((b * L_ + l) * H_ + h) * D_);
    float4 qa = q4[li * 2];
    float4 qb = q4[li * 2 + 1];

    const int* ip = idx + l * SK_;
    float mx = -CUDART_INF_F;
    float sm = 0.0f;
#pragma unroll
    for (int sg = 0; sg < 12; sg++) {
        int s = sg * 4 + g;
        bool valid = (s < SK_);
        int kr = ip[valid ? s : 0];
        const float4* k4 = (const float4*)(K + ((b * L_ + kr) * H_ + h) * D_);
        float4 ka = k4[li * 2];
        float4 kb = k4[li * 2 + 1];
        float d = qa.x * ka.x + qa.y * ka.y + qa.z * ka.z + qa.w * ka.w
                + qb.x * kb.x + qb.y * kb.y + qb.z * kb.z + qb.w * kb.w;
        d += __shfl_xor_sync(0xffffffffu, d, 4);
        d += __shfl_xor_sync(0xffffffffu, d, 2);
        d += __shfl_xor_sync(0xffffffffu, d, 1);
        if (valid) { mx = fmaxf(mx, d); sm += d; }
    }
    mx = fmaxf(mx, __shfl_xor_sync(0xffffffffu, mx, 8));
    mx = fmaxf(mx, __shfl_xor_sync(0xffffffffu, mx, 16));
    sm += __shfl_xor_sync(0xffffffffu, sm, 8);
    sm += __shfl_xor_sync(0xffffffffu, sm, 16);
    if (lane == 0) g_M[w] = mx - sm * (1.0f / (float)L_);
}

// ---------------------------------------------------------------------------
// Kernel 2: top-U per (b,h): two-level radix histogram + exact tail select.
// ---------------------------------------------------------------------------
__device__ __forceinline__ unsigned f2key(float f) {
    unsigned u = __float_as_uint(f);
    return (u & 0x80000000u) ? ~u : (u | 0x80000000u);
}

__global__ void __launch_bounds__(256) kernel_topk() {
    __shared__ unsigned skeys[L_];
    __shared__ int hist[256];
    __shared__ unsigned candKey[1024];
    __shared__ int candIdx[1024];
    __shared__ int sT1, sN1, sT2;
    __shared__ int cSel, cCand;
    __shared__ unsigned rk[256];
    __shared__ int ri[256];

    int bh = blockIdx.x;
    int t = threadIdx.x;
    const float* m = g_M + bh * L_;
    for (int i = t; i < L_; i += 256) skeys[i] = f2key(m[i]);
    hist[t] = 0;
    __syncthreads();

    for (int i = t; i < L_; i += 256) atomicAdd(&hist[skeys[i] >> 24], 1);
    __syncthreads();
    if (t == 0) {
        int acc = 0;
        for (int bin = 255; bin >= 0; bin--) {
            if (acc + hist[bin] >= U_) { sT1 = bin; sN1 = acc; break; }
            acc += hist[bin];
        }
    }
    __syncthreads();
    int T1 = sT1, n1 = sN1;
    hist[t] = 0;
    __syncthreads();

    for (int i = t; i < L_; i += 256)
        if ((int)(skeys[i] >> 24) == T1) atomicAdd(&hist[(skeys[i] >> 16) & 255], 1);
    __syncthreads();
    if (t == 0) {
        int acc = n1;
        for (int bin = 255; bin >= 0; bin--) {
            if (acc + hist[bin] >= U_) { sT2 = bin; break; }
            acc += hist[bin];
        }
        cSel = 0; cCand = 0;
    }
    __syncthreads();
    unsigned TH16 = ((unsigned)T1 << 8) | (unsigned)sT2;

    for (int i = t; i < L_; i += 256) {
        unsigned k16 = skeys[i] >> 16;
        if (k16 > TH16) {
            int pos = atomicAdd(&cSel, 1);
            g_Mtop[bh * U_ + pos] = i;
        } else if (k16 == TH16) {
            int pos = atomicAdd(&cCand, 1);
            if (pos < 1024) { candKey[pos] = skeys[i]; candIdx[pos] = i; }
        }
    }
    __syncthreads();
    int ndef = cSel;
    int need = U_ - ndef;
    int nc = (cCand < 1024) ? cCand : 1024;

    for (int it = 0; it < need; it++) {
        unsigned best = 0; int bi = -1;
        for (int jj = t; jj < nc; jj += 256) {
            unsigned v = candKey[jj];
            if (v > best) { best = v; bi = jj; }
        }
        rk[t] = best; ri[t] = bi;
        __syncthreads();
        for (int s = 128; s; s >>= 1) {
            if (t < s && rk[t + s] > rk[t]) { rk[t] = rk[t + s]; ri[t] = ri[t + s]; }
            __syncthreads();
        }
        if (t == 0) {
            g_Mtop[bh * U_ + ndef + it] = candIdx[ri[0]];
            candKey[ri[0]] = 0;
        }
        __syncthreads();
    }
}

// ---------------------------------------------------------------------------
// Kernel 3: V mean (zero + float4 partial sums)
// ---------------------------------------------------------------------------
__global__ void kernel_zero_mean() {
    int i = blockIdx.x * blockDim.x + threadIdx.x;
    if (i < B_ * H_ * D_) g_vmean[i] = 0.0f;
}

__global__ void __launch_bounds__(256) kernel_mean_part(const float* __restrict__ V) {
    int blk = blockIdx.x;              // 1024 blocks
    int seg = blk & 31;
    int bh = blk >> 5;
    int h = bh & (H_ - 1);
    int b = bh >> 3;
    int t = threadIdx.x;
    int d4 = t & 15;
    int sub = t >> 4;
    int l0 = seg * 128;
    const float4* V4 = (const float4*)V;
    float ax = 0.f, ay = 0.f, az = 0.f, aw = 0.f;
#pragma unroll
    for (int i = 0; i < 8; i++) {
        int l = l0 + sub + i * 16;
        float4 v = V4[((size_t)(b * L_ + l) * H_ + h) * 16 + d4];
        ax += v.x; ay += v.y; az += v.z; aw += v.w;
    }
    __shared__ float4 s[16][16];
    s[sub][d4] = make_float4(ax, ay, az, aw);
    __syncthreads();
    if (t < 16) {
        float tx = 0.f, ty = 0.f, tz = 0.f, tw = 0.f;
#pragma unroll
        for (int jj = 0; jj < 16; jj++) {
            float4 v = s[jj][t];
            tx += v.x; ty += v.y; tz += v.z; tw += v.w;
        }
        atomicAdd(&g_vmean[bh * D_ + t * 4 + 0], tx);
        atomicAdd(&g_vmean[bh * D_ + t * 4 + 1], ty);
        atomicAdd(&g_vmean[bh * D_ + t * 4 + 2], tz);
        atomicAdd(&g_vmean[bh * D_ + t * 4 + 3], tw);
    }
}

// ---------------------------------------------------------------------------
// Kernel 4: fill out with V-mean broadcast (float4 stores)
// ---------------------------------------------------------------------------
__global__ void kernel_fill(float* __restrict__ out) {
    unsigned i = blockIdx.x * blockDim.x + threadIdx.x;  // float4 index
    int d4 = i & 15;
    int h = (i >> 4) & 7;
    int b = i >> 19;
    const float4* vm4 = (const float4*)g_vmean;
    float4 v = vm4[(b * H_ + h) * 16 + d4];
    const float inv = 1.0f / (float)L_;
    ((float4*)out)[i] = make_float4(v.x * inv, v.y * inv, v.z * inv, v.w * inv);
}

// ---------------------------------------------------------------------------
// Kernel 5: split-KV attention, KC=128 per split, 32 splits.
// smem: sKT [64][132] (K^T), sV [128][68] (cp.async prefetch),
//       sQE [48][128] (Q rows stride 64, then E rows stride 128), sMt.
// Thread map: kt = t&15 (8 k's or 4 d's each), ut = t>>4 (3 u's each).
// ---------------------------------------------------------------------------
#define OFF_V   (64 * PADKT)                // 8448
#define OFF_QE  (OFF_V + KC * PADV)         // 8448 + 8704 = 17152
#define OFF_MT  (OFF_QE + 48 * KC)          // +6144 = 23296
#define SMEM_FLOATS (OFF_MT + 64)
#define SMEM_BYTES  (SMEM_FLOATS * 4)       // 93440 B

__global__ void __launch_bounds__(256) kernel_attn_part(
        const float* __restrict__ Q,
        const float* __restrict__ K,
        const float* __restrict__ V) {
    extern __shared__ float smem[];
    float* sKT = smem;                  // [64][PADKT]  K^T [d][k]
    float* sV  = smem + OFF_V;          // [KC][PADV]   V [k][d]
    float* sQE = smem + OFF_QE;         // Q [48][64], then E [48][128]
    int*   sMt = (int*)(smem + OFF_MT);

    int bh = blockIdx.x >> 5;
    int sp = blockIdx.x & 31;
    int h = bh & 7, b = bh >> 3;
    int k0 = sp * KC;
    int t = threadIdx.x;

    // Prefetch V (128 rows x 64 f): 8 x cp.async 16B per thread.
    {
        const char* vbase = (const char*)(V + ((size_t)(b * L_ + k0) * H_ + h) * D_);
#pragma unroll
        for (int i = 0; i < 8; i++) {
            int e = t + i * 256;               // [0,2048)
            int row = e >> 4, c = e & 15;
            unsigned dst = smem_u32(sV + row * PADV + c * 4);
            const char* src = vbase + (size_t)row * (H_ * D_ * 4) + c * 16;
            asm volatile("cp.async.cg.shared.global [%0], [%1], 16;"
                         :: "r"(dst), "l"(src));
        }
        asm volatile("cp.async.commit_group;");
    }

    if (t < U_) sMt[t] = g_Mtop[bh * U_ + t];
    __syncthreads();

    // Q rows (scattered gather, zero-pad to 48), stride-64 layout
#pragma unroll
    for (int i = 0; i < 3; i++) {
        int e = t + i * 256;                   // [0,768)
        int u = e >> 4, c = e & 15;
        float4 q = make_float4(0.f, 0.f, 0.f, 0.f);
        if (u < U_)
            q = *(const float4*)(Q + ((b * L_ + sMt[u]) * H_ + h) * D_ + c * 4);
        *(float4*)(sQE + u * 64 + c * 4) = q;
    }
    // K transposed: [d][k], k in [0,128)
#pragma unroll
    for (int i = 0; i < 32; i++) {
        int e = t + i * 256;                   // [0,8192)
        int k = e >> 6, d = e & 63;
        sKT[d * PADKT + k] = K[((b * L_ + k0 + k) * H_ + h) * D_ + d];
    }
    __syncthreads();

    int kt = t & 15, ut = t >> 4;
    int kk = kt * 8, u0 = ut * 3;

    // Phase 1: S[u][k] = sum_d q[u][d]*kT[d][k]  (3u x 8k per thread)
    ull acc[3][4];
#pragma unroll
    for (int jj = 0; jj < 3; jj++)
#pragma unroll
        for (int x = 0; x < 4; x++) acc[jj][x] = 0;
    {
        const float* q0p = sQE + (u0 + 0) * 64;
        const float* q1p = sQE + (u0 + 1) * 64;
        const float* q2p = sQE + (u0 + 2) * 64;
#pragma unroll 8
        for (int d = 0; d < 64; d++) {
            ulonglong2 ka = *(const ulonglong2*)&sKT[d * PADKT + kk];
            ulonglong2 kb = *(const ulonglong2*)&sKT[d * PADKT + kk + 4];
            ull q0, q1, q2;
            DUP2(q0, q0p[d]); DUP2(q1, q1p[d]); DUP2(q2, q2p[d]);
            FMA2(acc[0][0], q0, ka.x); FMA2(acc[0][1], q0, ka.y);
            FMA2(acc[0][2], q0, kb.x); FMA2(acc[0][3], q0, kb.y);
            FMA2(acc[1][0], q1, ka.x); FMA2(acc[1][1], q1, ka.y);
            FMA2(acc[1][2], q1, kb.x); FMA2(acc[1][3], q1, kb.y);
            FMA2(acc[2][0], q2, ka.x); FMA2(acc[2][1], q2, ka.y);
            FMA2(acc[2][2], q2, kb.x); FMA2(acc[2][3], q2, kb.y);
        }
    }

    // Phase 2 (registers): per-u softmax over 128 keys.
    // 16-thread group (kt 0..15 = half-warp lanes) holds the full row.
    float ev[3][8];
    {
        const float sc = 0.125f;
#pragma unroll
        for (int jj = 0; jj < 3; jj++) {
            float s[8];
#pragma unroll
            for (int x = 0; x < 4; x++) {
                s[2 * x] = lo2(acc[jj][x]) * sc;
                s[2 * x + 1] = hi2(acc[jj][x]) * sc;
            }
            float mm = s[0];
#pragma unroll
            for (int x = 1; x < 8; x++) mm = fmaxf(mm, s[x]);
            mm = fmaxf(mm, __shfl_xor_sync(0xffffffffu, mm, 1));
            mm = fmaxf(mm, __shfl_xor_sync(0xffffffffu, mm, 2));
            mm = fmaxf(mm, __shfl_xor_sync(0xffffffffu, mm, 4));
            mm = fmaxf(mm, __shfl_xor_sync(0xffffffffu, mm, 8));
            float ss = 0.0f;
#pragma unroll
            for (int x = 0; x < 8; x++) { ev[jj][x] = __expf(s[x] - mm); ss += ev[jj][x]; }
            ss += __shfl_xor_sync(0xffffffffu, ss, 1);
            ss += __shfl_xor_sync(0xffffffffu, ss, 2);
            ss += __shfl_xor_sync(0xffffffffu, ss, 4);
            ss += __shfl_xor_sync(0xffffffffu, ss, 8);
            int u = u0 + jj;
            if (kt == 0 && u < U_) {
                g_pm[(bh * NSPLIT + sp) * U_ + u] = mm;
                g_ps[(bh * NSPLIT + sp) * U_ + u] = ss;
            }
        }
    }
    __syncthreads();   // all Q reads done -> safe to overwrite sQE with E

#pragma unroll
    for (int jj = 0; jj < 3; jj++) {
        *(float4*)(sQE + (u0 + jj) * KC + kk) =
            make_float4(ev[jj][0], ev[jj][1], ev[jj][2], ev[jj][3]);
        *(float4*)(sQE + (u0 + jj) * KC + kk + 4) =
            make_float4(ev[jj][4], ev[jj][5], ev[jj][6], ev[jj][7]);
    }

    asm volatile("cp.async.wait_group 0;");
    __syncthreads();   // E visible + V arrived

    // Phase 3: AV[u][d] = sum_k E[u][k]*V[k][d]  (3u x 4d per thread)
    {
        int dd = kt * 4;
        ull c00 = 0, c01 = 0, c10 = 0, c11 = 0, c20 = 0, c21 = 0;
        const float* e0p = sQE + (u0 + 0) * KC;
        const float* e1p = sQE + (u0 + 1) * KC;
        const float* e2p = sQE + (u0 + 2) * KC;
#pragma unroll 8
        for (int k = 0; k < KC; k++) {
            ulonglong2 vv = *(const ulonglong2*)&sV[k * PADV + dd];
            ull e0, e1, e2;
            DUP2(e0, e0p[k]); DUP2(e1, e1p[k]); DUP2(e2, e2p[k]);
            FMA2(c00, e0, vv.x); FMA2(c01, e0, vv.y);
            FMA2(c10, e1, vv.x); FMA2(c11, e1, vv.y);
            FMA2(c20, e2, vv.x); FMA2(c21, e2, vv.y);
        }
        float* pa = g_pacc + (size_t)(bh * NSPLIT + sp) * U_ * D_;
        if (u0 + 0 < U_)
            *(float4*)&pa[(u0 + 0) * D_ + dd] =
                make_float4(lo2(c00), hi2(c00), lo2(c01), hi2(c01));
        if (u0 + 1 < U_)
            *(float4*)&pa[(u0 + 1) * D_ + dd] =
                make_float4(lo2(c10), hi2(c10), lo2(c11), hi2(c11));
        if (u0 + 2 < U_)
            *(float4*)&pa[(u0 + 2) * D_ + dd] =
                make_float4(lo2(c20), hi2(c20), lo2(c21), hi2(c21));
    }
}

// ---------------------------------------------------------------------------
// Kernel 6: combine 32 split partials. grid = (U_, B*H), 64 threads.
// ---------------------------------------------------------------------------
__global__ void __launch_bounds__(64) kernel_combine(float* __restrict__ out) {
    __shared__ float sw[NSPLIT];
    int u = blockIdx.x;
    int bh = blockIdx.y;
    int h = bh & 7, b = bh >> 3;
    int t = threadIdx.x;

    if (t < NSPLIT) {
        float m = g_pm[(bh * NSPLIT + t) * U_ + u];
        float s = g_ps[(bh * NSPLIT + t) * U_ + u];
        float mm = m;
#pragma unroll
        for (int o = 16; o; o >>= 1) mm = fmaxf(mm, __shfl_xor_sync(0xffffffffu, mm, o));
        float e = __expf(m - mm);
        float es = e * s;
#pragma unroll
        for (int o = 16; o; o >>= 1) es += __shfl_xor_sync(0xffffffffu, es, o);
        sw[t] = e / es;
    }
    __syncthreads();

    float acc = 0.0f;
    const float* pa = g_pacc + (size_t)bh * NSPLIT * U_ * D_ + u * D_ + t;
#pragma unroll 8
    for (int sp = 0; sp < NSPLIT; sp++)
        acc += pa[(size_t)sp * U_ * D_] * sw[sp];
    int lsel = g_Mtop[bh * U_ + u];
    out[((b * L_ + lsel) * H_ + h) * D_ + t] = acc;
}

// ---------------------------------------------------------------------------
extern "C" void kernel_launch(void* const* d_in, const int* in_sizes, int n_in,
                              void* d_out, int out_size) {
    const float* Q = (const float*)d_in[0];
    const float* K = (const float*)d_in[1];
    const float* V = (const float*)d_in[2];
    const int* idx = (const int*)d_in[3];   // int32 (JAX x64 disabled)
    float* out = (float*)d_out;

    cudaFuncSetAttribute((const void*)kernel_M,
                         cudaFuncAttributePreferredSharedMemoryCarveout, 0);
    cudaFuncSetAttribute((const void*)kernel_attn_part,
                         cudaFuncAttributeMaxDynamicSharedMemorySize, SMEM_BYTES);

    // Order: ncu capture slot (position 4) lands on kernel_attn_part.
    kernel_M<<<(B_ * H_ * L_) / 8, 256>>>(Q, K, idx);
    kernel_topk<<<B_ * H_, 256>>>();
    kernel_zero_mean<<<(B_ * H_ * D_ + 255) / 256, 256>>>();
    kernel_attn_part<<<B_ * H_ * NSPLIT, 256, SMEM_BYTES>>>(Q, K, V);
    kernel_mean_part<<<B_ * H_ * 32, 256>>>(V);
    kernel_fill<<<(B_ * L_ * H_ * D_ / 4 + 255) / 256, 256>>>(out);
    kernel_combine<<<dim3(U_, B_ * H_), 64>>>(out);
}

// round 10
// speedup vs baseline: 2.2104x; 1.0685x over previous
#include <cuda_runtime.h>
#include <math_constants.h>

// ProbAttention: B=4, L=4096, H=8, D=64, FACTOR=5
#define B_ 4
#define L_ 4096
#define H_ 8
#define D_ 64
#define SK_ 45
#define U_  45
#define NSPLIT 64
#define KC 64          // keys per split = L_/NSPLIT
#define PADK 68

// Scratch (device globals; no allocation allowed)
__device__ float g_M[B_ * H_ * L_];
__device__ int   g_Mtop[B_ * H_ * U_];
__device__ float g_vmean[B_ * H_ * D_];
__device__ float g_pm[B_ * H_ * NSPLIT * U_];
__device__ float g_ps[B_ * H_ * NSPLIT * U_];
__device__ float g_pacc[B_ * H_ * NSPLIT * U_ * D_];   // 23.6 MB

typedef unsigned long long ull;
__device__ __forceinline__ float lo2(ull v) { return __uint_as_float((unsigned)v); }
__device__ __forceinline__ float hi2(ull v) { return __uint_as_float((unsigned)(v >> 32)); }
#define FMA2(acc, a, b) asm("fma.rn.f32x2 %0, %1, %2, %0;" : "+l"(acc) : "l"(a), "l"(b))
#define DUP2(out, x) asm("mov.b64 %0, {%1, %1};" : "=l"(out) : "r"(__float_as_uint(x)))

__device__ __forceinline__ unsigned smem_u32(const void* p) {
    return (unsigned)__cvta_generic_to_shared(p);
}

// ---------------------------------------------------------------------------
// Kernel 1: M[b,h,l] = max_s(Q·K_s) - (1/L)*sum_s(Q·K_s)
// Gather version — measured AT the LTS cap (1.51 GB @ ~12 TB/s = 127us).
// ---------------------------------------------------------------------------
__global__ void __launch_bounds__(256) kernel_M(const float* __restrict__ Q,
                                                const float* __restrict__ K,
                                                const int* __restrict__ idx) {
    int j = (blockIdx.x * 111) & 16383;      // bijective remap
    int w = j * 8 + (threadIdx.x >> 5);
    int lane = threadIdx.x & 31;
    int li = lane & 7;
    int g  = lane >> 3;
    int l = w & (L_ - 1);
    int h = (w >> 12) & (H_ - 1);
    int b = w >> 15;

    const float4* q4 = (const float4*)(Q + ((b * L_ + l) * H_ + h) * D_);
    float4 qa = q4[li * 2];
    float4 qb = q4[li * 2 + 1];

    const int* ip = idx + l * SK_;
    float mx = -CUDART_INF_F;
    float sm = 0.0f;
#pragma unroll
    for (int sg = 0; sg < 12; sg++) {
        int s = sg * 4 + g;
        bool valid = (s < SK_);
        int kr = ip[valid ? s : 0];
        const float4* k4 = (const float4*)(K + ((b * L_ + kr) * H_ + h) * D_);
        float4 ka = k4[li * 2];
        float4 kb = k4[li * 2 + 1];
        float d = qa.x * ka.x + qa.y * ka.y + qa.z * ka.z + qa.w * ka.w
                + qb.x * kb.x + qb.y * kb.y + qb.z * kb.z + qb.w * kb.w;
        d += __shfl_xor_sync(0xffffffffu, d, 4);
        d += __shfl_xor_sync(0xffffffffu, d, 2);
        d += __shfl_xor_sync(0xffffffffu, d, 1);
        if (valid) { mx = fmaxf(mx, d); sm += d; }
    }
    mx = fmaxf(mx, __shfl_xor_sync(0xffffffffu, mx, 8));
    mx = fmaxf(mx, __shfl_xor_sync(0xffffffffu, mx, 16));
    sm += __shfl_xor_sync(0xffffffffu, sm, 8);
    sm += __shfl_xor_sync(0xffffffffu, sm, 16);
    if (lane == 0) g_M[w] = mx - sm * (1.0f / (float)L_);
}

// ---------------------------------------------------------------------------
// Kernel 2: top-U per (b,h): two-level radix histogram + exact tail select.
// ---------------------------------------------------------------------------
__device__ __forceinline__ unsigned f2key(float f) {
    unsigned u = __float_as_uint(f);
    return (u & 0x80000000u) ? ~u : (u | 0x80000000u);
}

__global__ void __launch_bounds__(256) kernel_topk() {
    __shared__ unsigned skeys[L_];
    __shared__ int hist[256];
    __shared__ unsigned candKey[1024];
    __shared__ int candIdx[1024];
    __shared__ int sT1, sN1, sT2;
    __shared__ int cSel, cCand;
    __shared__ unsigned rk[256];
    __shared__ int ri[256];

    int bh = blockIdx.x;
    int t = threadIdx.x;
    const float* m = g_M + bh * L_;
    for (int i = t; i < L_; i += 256) skeys[i] = f2key(m[i]);
    hist[t] = 0;
    __syncthreads();

    for (int i = t; i < L_; i += 256) atomicAdd(&hist[skeys[i] >> 24], 1);
    __syncthreads();
    if (t == 0) {
        int acc = 0;
        for (int bin = 255; bin >= 0; bin--) {
            if (acc + hist[bin] >= U_) { sT1 = bin; sN1 = acc; break; }
            acc += hist[bin];
        }
    }
    __syncthreads();
    int T1 = sT1, n1 = sN1;
    hist[t] = 0;
    __syncthreads();

    for (int i = t; i < L_; i += 256)
        if ((int)(skeys[i] >> 24) == T1) atomicAdd(&hist[(skeys[i] >> 16) & 255], 1);
    __syncthreads();
    if (t == 0) {
        int acc = n1;
        for (int bin = 255; bin >= 0; bin--) {
            if (acc + hist[bin] >= U_) { sT2 = bin; break; }
            acc += hist[bin];
        }
        cSel = 0; cCand = 0;
    }
    __syncthreads();
    unsigned TH16 = ((unsigned)T1 << 8) | (unsigned)sT2;

    for (int i = t; i < L_; i += 256) {
        unsigned k16 = skeys[i] >> 16;
        if (k16 > TH16) {
            int pos = atomicAdd(&cSel, 1);
            g_Mtop[bh * U_ + pos] = i;
        } else if (k16 == TH16) {
            int pos = atomicAdd(&cCand, 1);
            if (pos < 1024) { candKey[pos] = skeys[i]; candIdx[pos] = i; }
        }
    }
    __syncthreads();
    int ndef = cSel;
    int need = U_ - ndef;
    int nc = (cCand < 1024) ? cCand : 1024;

    for (int it = 0; it < need; it++) {
        unsigned best = 0; int bi = -1;
        for (int jj = t; jj < nc; jj += 256) {
            unsigned v = candKey[jj];
            if (v > best) { best = v; bi = jj; }
        }
        rk[t] = best; ri[t] = bi;
        __syncthreads();
        for (int s = 128; s; s >>= 1) {
            if (t < s && rk[t + s] > rk[t]) { rk[t] = rk[t + s]; ri[t] = ri[t + s]; }
            __syncthreads();
        }
        if (t == 0) {
            g_Mtop[bh * U_ + ndef + it] = candIdx[ri[0]];
            candKey[ri[0]] = 0;
        }
        __syncthreads();
    }
}

// ---------------------------------------------------------------------------
// Kernel 3: V mean (zero + float4 partial sums)
// ---------------------------------------------------------------------------
__global__ void kernel_zero_mean() {
    int i = blockIdx.x * blockDim.x + threadIdx.x;
    if (i < B_ * H_ * D_) g_vmean[i] = 0.0f;
}

__global__ void __launch_bounds__(256) kernel_mean_part(const float* __restrict__ V) {
    int blk = blockIdx.x;              // 1024 blocks
    int seg = blk & 31;
    int bh = blk >> 5;
    int h = bh & (H_ - 1);
    int b = bh >> 3;
    int t = threadIdx.x;
    int d4 = t & 15;
    int sub = t >> 4;
    int l0 = seg * 128;
    const float4* V4 = (const float4*)V;
    float ax = 0.f, ay = 0.f, az = 0.f, aw = 0.f;
#pragma unroll
    for (int i = 0; i < 8; i++) {
        int l = l0 + sub + i * 16;
        float4 v = V4[((size_t)(b * L_ + l) * H_ + h) * 16 + d4];
        ax += v.x; ay += v.y; az += v.z; aw += v.w;
    }
    __shared__ float4 s[16][16];
    s[sub][d4] = make_float4(ax, ay, az, aw);
    __syncthreads();
    if (t < 16) {
        float tx = 0.f, ty = 0.f, tz = 0.f, tw = 0.f;
#pragma unroll
        for (int jj = 0; jj < 16; jj++) {
            float4 v = s[jj][t];
            tx += v.x; ty += v.y; tz += v.z; tw += v.w;
        }
        atomicAdd(&g_vmean[bh * D_ + t * 4 + 0], tx);
        atomicAdd(&g_vmean[bh * D_ + t * 4 + 1], ty);
        atomicAdd(&g_vmean[bh * D_ + t * 4 + 2], tz);
        atomicAdd(&g_vmean[bh * D_ + t * 4 + 3], tw);
    }
}

// ---------------------------------------------------------------------------
// Kernel 4: fill out with V-mean broadcast (float4 stores)
// ---------------------------------------------------------------------------
__global__ void kernel_fill(float* __restrict__ out) {
    unsigned i = blockIdx.x * blockDim.x + threadIdx.x;  // float4 index
    int d4 = i & 15;
    int h = (i >> 4) & 7;
    int b = i >> 19;
    const float4* vm4 = (const float4*)g_vmean;
    float4 v = vm4[(b * H_ + h) * 16 + d4];
    const float inv = 1.0f / (float)L_;
    ((float4*)out)[i] = make_float4(v.x * inv, v.y * inv, v.z * inv, v.w * inv);
}

// ---------------------------------------------------------------------------
// Kernel 5: split-KV attention (round-6 version: NSPLIT=64, KC=64).
// cp.async V prefetch; register softmax; f32x2 FMAs.
// ---------------------------------------------------------------------------
#define OFF_V   (64 * PADK)
#define OFF_QE  (OFF_V + 64 * PADK)
#define OFF_MT  (OFF_QE + 48 * 64)
#define SMEM_FLOATS (OFF_MT + 64)
#define SMEM_BYTES  (SMEM_FLOATS * 4)

__global__ void __launch_bounds__(256) kernel_attn_part(
        const float* __restrict__ Q,
        const float* __restrict__ K,
        const float* __restrict__ V) {
    extern __shared__ float smem[];
    float* sKT = smem;                  // [64][PADK]  K transposed [d][k]
    float* sV  = smem + OFF_V;          // [64][PADK]  V natural   [k][d]
    float* sQE = smem + OFF_QE;         // [48][64]    Q rows, then E rows
    int*   sMt = (int*)(smem + OFF_MT);

    int bh = blockIdx.x >> 6;
    int sp = blockIdx.x & 63;
    int h = bh & 7, b = bh >> 3;
    int k0 = sp * KC;
    int t = threadIdx.x;

    {
        const char* vbase = (const char*)(V + ((size_t)(b * L_ + k0) * H_ + h) * D_);
#pragma unroll
        for (int i = 0; i < 4; i++) {
            int e = t + i * 256;
            int row = e >> 4, c = e & 15;
            unsigned dst = smem_u32(sV + row * PADK + c * 4);
            const char* src = vbase + (size_t)row * (H_ * D_ * 4) + c * 16;
            asm volatile("cp.async.cg.shared.global [%0], [%1], 16;"
                         :: "r"(dst), "l"(src));
        }
        asm volatile("cp.async.commit_group;");
    }

    if (t < U_) sMt[t] = g_Mtop[bh * U_ + t];
    __syncthreads();

#pragma unroll
    for (int i = 0; i < 3; i++) {
        int e = t + i * 256;
        int u = e >> 4, c = e & 15;
        float4 q = make_float4(0.f, 0.f, 0.f, 0.f);
        if (u < U_)
            q = *(const float4*)(Q + ((b * L_ + sMt[u]) * H_ + h) * D_ + c * 4);
        *(float4*)(sQE + u * 64 + c * 4) = q;
    }
#pragma unroll
    for (int i = 0; i < 16; i++) {
        int e = t + i * 256;
        int k = e >> 6, d = e & 63;
        sKT[d * PADK + k] = K[((b * L_ + k0 + k) * H_ + h) * D_ + d];
    }
    __syncthreads();

    int kt = t & 15, ut = t >> 4;
    int kk = kt * 4, u0 = ut * 3;

    ull a00 = 0, a01 = 0, a10 = 0, a11 = 0, a20 = 0, a21 = 0;
    {
        const float* q0p = sQE + (u0 + 0) * 64;
        const float* q1p = sQE + (u0 + 1) * 64;
        const float* q2p = sQE + (u0 + 2) * 64;
#pragma unroll 8
        for (int d = 0; d < 64; d++) {
            ulonglong2 kv = *(const ulonglong2*)&sKT[d * PADK + kk];
            ull q0, q1, q2;
            DUP2(q0, q0p[d]); DUP2(q1, q1p[d]); DUP2(q2, q2p[d]);
            FMA2(a00, q0, kv.x); FMA2(a01, q0, kv.y);
            FMA2(a10, q1, kv.x); FMA2(a11, q1, kv.y);
            FMA2(a20, q2, kv.x); FMA2(a21, q2, kv.y);
        }
    }

    float ev[3][4];
    {
        const float sc = 0.125f;
        ull ra[3][2] = {{a00, a01}, {a10, a11}, {a20, a21}};
#pragma unroll
        for (int jj = 0; jj < 3; jj++) {
            float s0 = lo2(ra[jj][0]) * sc, s1 = hi2(ra[jj][0]) * sc;
            float s2 = lo2(ra[jj][1]) * sc, s3 = hi2(ra[jj][1]) * sc;
            float mm = fmaxf(fmaxf(s0, s1), fmaxf(s2, s3));
            mm = fmaxf(mm, __shfl_xor_sync(0xffffffffu, mm, 1));
            mm = fmaxf(mm, __shfl_xor_sync(0xffffffffu, mm, 2));
            mm = fmaxf(mm, __shfl_xor_sync(0xffffffffu, mm, 4));
            mm = fmaxf(mm, __shfl_xor_sync(0xffffffffu, mm, 8));
            float e0 = __expf(s0 - mm), e1 = __expf(s1 - mm);
            float e2 = __expf(s2 - mm), e3 = __expf(s3 - mm);
            float ss = (e0 + e1) + (e2 + e3);
            ss += __shfl_xor_sync(0xffffffffu, ss, 1);
            ss += __shfl_xor_sync(0xffffffffu, ss, 2);
            ss += __shfl_xor_sync(0xffffffffu, ss, 4);
            ss += __shfl_xor_sync(0xffffffffu, ss, 8);
            ev[jj][0] = e0; ev[jj][1] = e1; ev[jj][2] = e2; ev[jj][3] = e3;
            int u = u0 + jj;
            if (kt == 0 && u < U_) {
                g_pm[(bh * NSPLIT + sp) * U_ + u] = mm;
                g_ps[(bh * NSPLIT + sp) * U_ + u] = ss;
            }
        }
    }
    __syncthreads();

#pragma unroll
    for (int jj = 0; jj < 3; jj++)
        *(float4*)(sQE + (u0 + jj) * 64 + kk) =
            make_float4(ev[jj][0], ev[jj][1], ev[jj][2], ev[jj][3]);

    asm volatile("cp.async.wait_group 0;");
    __syncthreads();

    {
        int dd = kk;
        ull c00 = 0, c01 = 0, c10 = 0, c11 = 0, c20 = 0, c21 = 0;
        const float* e0p = sQE + (u0 + 0) * 64;
        const float* e1p = sQE + (u0 + 1) * 64;
        const float* e2p = sQE + (u0 + 2) * 64;
#pragma unroll 8
        for (int k = 0; k < 64; k++) {
            ulonglong2 vv = *(const ulonglong2*)&sV[k * PADK + dd];
            ull e0, e1, e2;
            DUP2(e0, e0p[k]); DUP2(e1, e1p[k]); DUP2(e2, e2p[k]);
            FMA2(c00, e0, vv.x); FMA2(c01, e0, vv.y);
            FMA2(c10, e1, vv.x); FMA2(c11, e1, vv.y);
            FMA2(c20, e2, vv.x); FMA2(c21, e2, vv.y);
        }
        float* pa = g_pacc + (size_t)(bh * NSPLIT + sp) * U_ * D_;
        if (u0 + 0 < U_)
            *(float4*)&pa[(u0 + 0) * D_ + dd] =
                make_float4(lo2(c00), hi2(c00), lo2(c01), hi2(c01));
        if (u0 + 1 < U_)
            *(float4*)&pa[(u0 + 1) * D_ + dd] =
                make_float4(lo2(c10), hi2(c10), lo2(c11), hi2(c11));
        if (u0 + 2 < U_)
            *(float4*)&pa[(u0 + 2) * D_ + dd] =
                make_float4(lo2(c20), hi2(c20), lo2(c21), hi2(c21));
    }
}

// ---------------------------------------------------------------------------
// Kernel 6: combine partials. grid = (U_, B*H), 64 threads.
// ---------------------------------------------------------------------------
__global__ void __launch_bounds__(64) kernel_combine(float* __restrict__ out) {
    __shared__ float sw[NSPLIT];
    __shared__ float red[64];
    int u = blockIdx.x;
    int bh = blockIdx.y;
    int h = bh & 7, b = bh >> 3;
    int t = threadIdx.x;

    float m = g_pm[(bh * NSPLIT + t) * U_ + u];
    float s = g_ps[(bh * NSPLIT + t) * U_ + u];
    red[t] = m;
    __syncthreads();
    for (int st = 32; st; st >>= 1) {
        if (t < st) red[t] = fmaxf(red[t], red[t + st]);
        __syncthreads();
    }
    float M = red[0];
    __syncthreads();
    float e = __expf(m - M);
    red[t] = e * s;
    __syncthreads();
    for (int st = 32; st; st >>= 1) {
        if (t < st) red[t] += red[t + st];
        __syncthreads();
    }
    float inv = 1.0f / red[0];
    sw[t] = e * inv;
    __syncthreads();

    float acc = 0.0f;
    const float* pa = g_pacc + (size_t)bh * NSPLIT * U_ * D_ + u * D_ + t;
#pragma unroll 8
    for (int sp = 0; sp < NSPLIT; sp++)
        acc += pa[(size_t)sp * U_ * D_] * sw[sp];
    int lsel = g_Mtop[bh * U_ + u];
    out[((b * L_ + lsel) * H_ + h) * D_ + t] = acc;
}

// ---------------------------------------------------------------------------
// Launch: two streams. Main chain (M -> topk -> attn) on the caller stream;
// side chain (zero -> mean -> fill) on s2, forked/joined with events so the
// captured graph runs them concurrently. combine waits on both.
// ---------------------------------------------------------------------------
extern "C" void kernel_launch(void* const* d_in, const int* in_sizes, int n_in,
                              void* d_out, int out_size) {
    const float* Q = (const float*)d_in[0];
    const float* K = (const float*)d_in[1];
    const float* V = (const float*)d_in[2];
    const int* idx = (const int*)d_in[3];   // int32 (JAX x64 disabled)
    float* out = (float*)d_out;

    static cudaStream_t s2 = nullptr;
    static cudaEvent_t evFork = nullptr, evJoin = nullptr;
    if (s2 == nullptr) {
        cudaStreamCreateWithFlags(&s2, cudaStreamNonBlocking);
        cudaEventCreateWithFlags(&evFork, cudaEventDisableTiming);
        cudaEventCreateWithFlags(&evJoin, cudaEventDisableTiming);
        cudaFuncSetAttribute((const void*)kernel_M,
                             cudaFuncAttributePreferredSharedMemoryCarveout, 0);
        cudaFuncSetAttribute((const void*)kernel_attn_part,
                             cudaFuncAttributeMaxDynamicSharedMemorySize, SMEM_BYTES);
    }

    // Fork side stream off the (possibly capturing) legacy stream.
    cudaEventRecord(evFork, 0);
    cudaStreamWaitEvent(s2, evFork, 0);

    // Main chain (submissions 1,2; slot-4 ncu capture lands on attn below)
    kernel_M<<<(B_ * H_ * L_) / 8, 256>>>(Q, K, idx);
    kernel_topk<<<B_ * H_, 256>>>();

    // Side chain on s2 (runs concurrently with kernel_M)
    kernel_zero_mean<<<(B_ * H_ * D_ + 255) / 256, 256, 0, s2>>>();

    // submission 4: attn (main chain)
    kernel_attn_part<<<B_ * H_ * NSPLIT, 256, SMEM_BYTES>>>(Q, K, V);

    kernel_mean_part<<<B_ * H_ * 32, 256, 0, s2>>>(V);
    kernel_fill<<<(B_ * L_ * H_ * D_ / 4 + 255) / 256, 256, 0, s2>>>(out);

    // Join side stream back, then combine (needs pacc + fill-complete).
    cudaEventRecord(evJoin, s2);
    cudaStreamWaitEvent(0, evJoin, 0);
    kernel_combine<<<dim3(U_, B_ * H_), 64>>>(out);
}